// round 16
// baseline (speedup 1.0000x reference)
#include <cuda_runtime.h>
#include <cuda_fp16.h>
#include <cstdint>

#define N_MAX 100000
#define E_MAX 1600000
#define IN_C 64
#define HID_C 64
#define OUT_C 32
#define FULL 0xffffffffu
#define M_SHIFT 16.0f   // constant softmax shift (shift-invariant; scores are O(10))

// ---------------- scratch (no allocations; statics zero-init at load) ----------------
__device__ int   g_cnt[N_MAX];            // hist; zeroed by scan after reading
__device__ int   g_cur[N_MAX];            // fill cursors; zeroed by agg
__device__ int   g_off[N_MAX + 1];
__device__ int   g_adj[E_MAX];            // CSR adjacency (src grouped by dst)
__device__ unsigned long long g_tstate[128];  // lookback states (reset in prep)
__device__ __align__(16) __half g_xh[N_MAX * IN_C];     // fp16 x
__device__ __align__(16) __half g_aggh[N_MAX * IN_C];   // fp16 mean-agg
__device__ __align__(16) __half g_zh[N_MAX * OUT_C];    // fp16 z
__device__ float g_as[N_MAX];
__device__ float g_ad[N_MAX];

__device__ __forceinline__ float lrelu(float v) {
    return v > 0.0f ? v : 0.2f * v;
}

// packed f32x2 helpers (Blackwell)
__device__ __forceinline__ void fma2(unsigned long long& d,
                                     unsigned long long a,
                                     unsigned long long b) {
    asm("fma.rn.f32x2 %0, %1, %2, %0;" : "+l"(d) : "l"(a), "l"(b));
}
__device__ __forceinline__ void add2(unsigned long long& d, unsigned long long a) {
    asm("add.rn.f32x2 %0, %0, %1;" : "+l"(d) : "l"(a));
}
__device__ __forceinline__ unsigned long long pack2(float v) {
    unsigned long long r;
    asm("mov.b64 %0, {%1, %1};" : "=l"(r) : "f"(v));
    return r;
}
__device__ __forceinline__ unsigned long long packf(float a, float b) {
    unsigned long long r;
    asm("mov.b64 %0, {%1, %2};" : "=l"(r) : "f"(a), "f"(b));
    return r;
}
__device__ __forceinline__ float2 unpack2(unsigned long long v) {
    float2 f;
    asm("mov.b64 {%0, %1}, %2;" : "=f"(f.x), "=f"(f.y) : "l"(v));
    return f;
}
// half2 (as uint) -> packed f32x2
__device__ __forceinline__ unsigned long long h2tof2(unsigned h2) {
    __half2 h = *reinterpret_cast<__half2*>(&h2);
    float2 f = __half22float2(h);
    return packf(f.x, f.y);
}

// packed accumulate: 8 halves into 4 f32x2 accumulators
__device__ __forceinline__ void acc8p(uint4 u, unsigned long long* a) {
    add2(a[0], h2tof2(u.x));
    add2(a[1], h2tof2(u.y));
    add2(a[2], h2tof2(u.z));
    add2(a[3], h2tof2(u.w));
}
// packed fma: 8 halves * broadcast w into 4 f32x2 accumulators
__device__ __forceinline__ void fma8p(uint4 u, unsigned long long w2,
                                      unsigned long long* a) {
    fma2(a[0], h2tof2(u.x), w2);
    fma2(a[1], h2tof2(u.y), w2);
    fma2(a[2], h2tof2(u.z), w2);
    fma2(a[3], h2tof2(u.w), w2);
}

// unpack uint4 of 8 halves into 4 packed f32x2 regs
__device__ __forceinline__ void h8_to_f32x2(uint4 u, unsigned long long* o) {
    o[0] = h2tof2(u.x);
    o[1] = h2tof2(u.y);
    o[2] = h2tof2(u.z);
    o[3] = h2tof2(u.w);
}

// ---------------- K1: prep = cvt(x->fp16) + hist(dst) + tstate reset ----------------
__global__ void k_prep(const float* __restrict__ x,
                       const int* __restrict__ dst,
                       int E, int totalx) {
    int i = blockIdx.x * blockDim.x + threadIdx.x;
    if (blockIdx.x == 0 && threadIdx.x < 128) g_tstate[threadIdx.x] = 0ull;

    int i8 = i * 8;
    if (i8 < totalx) {
        float4 a = *reinterpret_cast<const float4*>(x + i8);
        float4 b = *reinterpret_cast<const float4*>(x + i8 + 4);
        __half2 h[4];
        h[0] = __floats2half2_rn(a.x, a.y);
        h[1] = __floats2half2_rn(a.z, a.w);
        h[2] = __floats2half2_rn(b.x, b.y);
        h[3] = __floats2half2_rn(b.z, b.w);
        *reinterpret_cast<uint4*>(g_xh + i8) = *reinterpret_cast<uint4*>(h);
    }
    unsigned e = (unsigned)i * 4u;
    if (e + 4 <= (unsigned)E) {
        int4 d = *reinterpret_cast<const int4*>(dst + e);
        atomicAdd(&g_cnt[d.x], 1);
        atomicAdd(&g_cnt[d.y], 1);
        atomicAdd(&g_cnt[d.z], 1);
        atomicAdd(&g_cnt[d.w], 1);
    } else {
        for (; e < (unsigned)E; e++) atomicAdd(&g_cnt[dst[e]], 1);
    }
}

// ---------------- K2: single-launch decoupled-lookback exclusive scan ----------------
__global__ void __launch_bounds__(1024) k_scan_lb(int n, int nb) {
    __shared__ int wsum[32];
    __shared__ int s_excl;
    int b = blockIdx.x, t = threadIdx.x;
    int lane = t & 31, w = t >> 5;
    int i = b * 1024 + t;

    int v = (i < n) ? g_cnt[i] : 0;
    if (i < n) g_cnt[i] = 0;          // reset for next replay

    int incl = v;
#pragma unroll
    for (int o = 1; o < 32; o <<= 1) {
        int u = __shfl_up_sync(FULL, incl, o);
        if (lane >= o) incl += u;
    }
    if (lane == 31) wsum[w] = incl;
    __syncthreads();
    if (w == 0) {
        int s = wsum[lane];
#pragma unroll
        for (int o = 1; o < 32; o <<= 1) {
            int u = __shfl_up_sync(FULL, s, o);
            if (lane >= o) s += u;
        }
        wsum[lane] = s;
    }
    __syncthreads();
    int blockIncl = incl + (w > 0 ? wsum[w - 1] : 0);
    int total = wsum[31];

    if (t == 0)
        atomicExch(&g_tstate[b], (1ull << 32) | (unsigned long long)(unsigned)total);

    if (t == 0 && b == 0) s_excl = 0;
    if (b > 0 && w == 0) {
        int excl = 0;
        int hi = b - 1;
        while (true) {
            int idx = hi - lane;
            unsigned long long s = 0;
            int st = 0;
            if (idx >= 0) {
                do {
                    s = *(volatile unsigned long long*)&g_tstate[idx];
                    st = (int)(s >> 32);
                } while (st == 0);
            }
            unsigned pm = __ballot_sync(FULL, idx >= 0 && st == 2);
            int val = (idx >= 0) ? (int)(unsigned)s : 0;
            if (pm) {
                int fl = __ffs(pm) - 1;
                int contrib = (lane <= fl) ? val : 0;
#pragma unroll
                for (int o = 16; o > 0; o >>= 1)
                    contrib += __shfl_xor_sync(FULL, contrib, o);
                excl += contrib;
                break;
            } else {
                int contrib = val;
#pragma unroll
                for (int o = 16; o > 0; o >>= 1)
                    contrib += __shfl_xor_sync(FULL, contrib, o);
                excl += contrib;
                hi -= 32;
                if (hi < 0) break;
            }
        }
        if (lane == 0) s_excl = excl;
    }
    __syncthreads();
    int excl = s_excl;

    if (t == 0)
        atomicExch(&g_tstate[b],
                   (2ull << 32) | (unsigned long long)(unsigned)(excl + total));

    if (i < n) g_off[i] = excl + blockIncl - v;
    if (b == nb - 1 && t == 1023) g_off[n] = excl + total;
}

// ---------------- K3: fill adjacency (4 edges/thread) ----------------
__global__ void k_fill(const int* __restrict__ src,
                       const int* __restrict__ dst,
                       int E) {
    unsigned i = (blockIdx.x * blockDim.x + threadIdx.x) * 4u;
    if (i + 4 <= (unsigned)E) {
        int4 d = *reinterpret_cast<const int4*>(dst + i);
        int4 s = *reinterpret_cast<const int4*>(src + i);
        g_adj[g_off[d.x] + atomicAdd(&g_cur[d.x], 1)] = s.x;
        g_adj[g_off[d.y] + atomicAdd(&g_cur[d.y], 1)] = s.y;
        g_adj[g_off[d.z] + atomicAdd(&g_cur[d.z], 1)] = s.z;
        g_adj[g_off[d.w] + atomicAdd(&g_cur[d.w], 1)] = s.w;
    } else {
        for (; i < (unsigned)E; i++) {
            int d = dst[i];
            g_adj[g_off[d] + atomicAdd(&g_cur[d], 1)] = src[i];
        }
    }
}

// ---------------- K4: mean aggregation — packed f32x2 accumulate ----------------
__global__ void k_agg(int n) {
    int node = (blockIdx.x * blockDim.x + threadIdx.x) >> 5;
    int lane = threadIdx.x & 31;
    if (node >= n) return;
    int beg = g_off[node];
    int cnt = g_off[node + 1] - beg;
    if (lane == 0) g_cur[node] = 0;     // reset cursor for next replay
    int grp = lane >> 3;    // 0..3
    int q = lane & 7;       // 0..7

    unsigned long long aA[4] = {0ull, 0ull, 0ull, 0ull};
    unsigned long long aB[4] = {0ull, 0ull, 0ull, 0ull};

    for (int base = 0; base < cnt; base += 32) {
        int kk = base + lane;
        int s_l = (kk < cnt) ? g_adj[beg + kk] : 0;
        int lim = min(cnt - base, 32);
        for (int k = 0; k < lim; k += 8) {
            int i0 = k + grp;
            int i1 = k + 4 + grp;
            int s0 = __shfl_sync(FULL, s_l, i0 & 31);
            int s1 = __shfl_sync(FULL, s_l, i1 & 31);
            if (i0 < lim) {
                uint4 u = *reinterpret_cast<const uint4*>(g_xh + (size_t)s0 * IN_C + q * 8);
                acc8p(u, aA);
            }
            if (i1 < lim) {
                uint4 u = *reinterpret_cast<const uint4*>(g_xh + (size_t)s1 * IN_C + q * 8);
                acc8p(u, aB);
            }
        }
    }
    float r[8];
#pragma unroll
    for (int i = 0; i < 4; i++) {
        float2 fa = unpack2(aA[i]);
        float2 fb = unpack2(aB[i]);
        r[2 * i] = fa.x + fb.x;
        r[2 * i + 1] = fa.y + fb.y;
    }
#pragma unroll
    for (int i = 0; i < 8; i++) {
        r[i] += __shfl_xor_sync(FULL, r[i], 8);
        r[i] += __shfl_xor_sync(FULL, r[i], 16);
    }
    float inv = 1.0f / fmaxf((float)cnt, 1.0f);
    if (lane < 8) {
        __half2 h[4];
        h[0] = __floats2half2_rn(r[0] * inv, r[1] * inv);
        h[1] = __floats2half2_rn(r[2] * inv, r[3] * inv);
        h[2] = __floats2half2_rn(r[4] * inv, r[5] * inv);
        h[3] = __floats2half2_rn(r[6] * inv, r[7] * inv);
        *reinterpret_cast<uint4*>(g_aggh + (size_t)node * IN_C + q * 8) =
            *reinterpret_cast<uint4*>(h);
    }
}

// ---------------- K5: node forward GEMM — fp16 inputs/h, 128-node tile, 8x8 ----------------
__global__ void __launch_bounds__(128) k_forward(
        const float* __restrict__ W_l,
        const float* __restrict__ W_r,
        const float* __restrict__ b1,
        const float* __restrict__ W_g,
        const float* __restrict__ att_src,
        const float* __restrict__ att_dst,
        int n) {
    extern __shared__ char smraw[];
    __half* sInH = reinterpret_cast<__half*>(smraw);           // 32KB
    float* sW = reinterpret_cast<float*>(smraw + 32768);       // 32KB
    float* sWg = reinterpret_cast<float*>(smraw + 65536);      // 8KB

    int tid = threadIdx.x;
    int node0 = blockIdx.x * 128;

    for (int i = tid; i < 2048; i += 128) {
        int k = i >> 4, q = i & 15;
        const float* sp = (k < 64) ? (W_l + k * 64 + q * 4)
                                   : (W_r + (k - 64) * 64 + q * 4);
        *reinterpret_cast<float4*>(&sW[k * 64 + q * 4]) =
            *reinterpret_cast<const float4*>(sp);
    }
    for (int i = tid; i < 512; i += 128) {
        int k = i >> 3, q = i & 7;
        *reinterpret_cast<float4*>(&sWg[k * 32 + q * 4]) =
            *reinterpret_cast<const float4*>(W_g + k * 32 + q * 4);
    }
    for (int i = tid; i < 1024; i += 128) {
        int c = i >> 6, p = i & 63;
        int n0 = node0 + 2 * p;
        uint4 a = make_uint4(0, 0, 0, 0), b = make_uint4(0, 0, 0, 0);
        if (n0 < n)
            a = (c < 8) ? *reinterpret_cast<const uint4*>(g_aggh + (size_t)n0 * IN_C + c * 8)
                        : *reinterpret_cast<const uint4*>(g_xh + (size_t)n0 * IN_C + (c - 8) * 8);
        if (n0 + 1 < n)
            b = (c < 8) ? *reinterpret_cast<const uint4*>(g_aggh + (size_t)(n0 + 1) * IN_C + c * 8)
                        : *reinterpret_cast<const uint4*>(g_xh + (size_t)(n0 + 1) * IN_C + (c - 8) * 8);
        const __half* ha = reinterpret_cast<const __half*>(&a);
        const __half* hb = reinterpret_cast<const __half*>(&b);
        int kb = c * 8;
#pragma unroll
        for (int j = 0; j < 8; j++)
            *reinterpret_cast<__half2*>(&sInH[(kb + j) * 128 + 2 * p]) =
                __halves2half2(ha[j], hb[j]);
    }
    __syncthreads();

    int ng = tid & 15;
    int cg = tid >> 4;
    int ngb = ng * 8;
    int cb = cg * 8;

    unsigned long long acc[8][4];
#pragma unroll
    for (int c = 0; c < 8; c++)
#pragma unroll
        for (int p = 0; p < 4; p++) acc[c][p] = 0ull;

    for (int k = 0; k < 128; k++) {
        uint4 inu = *reinterpret_cast<const uint4*>(&sInH[k * 128 + ngb]);
        unsigned long long in[4];
        h8_to_f32x2(inu, in);
        float4 wA = *reinterpret_cast<const float4*>(&sW[k * 64 + cb]);
        float4 wB = *reinterpret_cast<const float4*>(&sW[k * 64 + cb + 4]);
        unsigned long long w0 = pack2(wA.x), w1 = pack2(wA.y);
        unsigned long long w2 = pack2(wA.z), w3 = pack2(wA.w);
        unsigned long long w4 = pack2(wB.x), w5 = pack2(wB.y);
        unsigned long long w6 = pack2(wB.z), w7 = pack2(wB.w);
        fma2(acc[0][0], in[0], w0); fma2(acc[0][1], in[1], w0);
        fma2(acc[0][2], in[2], w0); fma2(acc[0][3], in[3], w0);
        fma2(acc[1][0], in[0], w1); fma2(acc[1][1], in[1], w1);
        fma2(acc[1][2], in[2], w1); fma2(acc[1][3], in[3], w1);
        fma2(acc[2][0], in[0], w2); fma2(acc[2][1], in[1], w2);
        fma2(acc[2][2], in[2], w2); fma2(acc[2][3], in[3], w2);
        fma2(acc[3][0], in[0], w3); fma2(acc[3][1], in[1], w3);
        fma2(acc[3][2], in[2], w3); fma2(acc[3][3], in[3], w3);
        fma2(acc[4][0], in[0], w4); fma2(acc[4][1], in[1], w4);
        fma2(acc[4][2], in[2], w4); fma2(acc[4][3], in[3], w4);
        fma2(acc[5][0], in[0], w5); fma2(acc[5][1], in[1], w5);
        fma2(acc[5][2], in[2], w5); fma2(acc[5][3], in[3], w5);
        fma2(acc[6][0], in[0], w6); fma2(acc[6][1], in[1], w6);
        fma2(acc[6][2], in[2], w6); fma2(acc[6][3], in[3], w6);
        fma2(acc[7][0], in[0], w7); fma2(acc[7][1], in[1], w7);
        fma2(acc[7][2], in[2], w7); fma2(acc[7][3], in[3], w7);
    }
    __syncthreads();

    __half* sHh = sInH;
    float b1v[8];
#pragma unroll
    for (int c = 0; c < 8; c++) b1v[c] = b1[cb + c];
#pragma unroll
    for (int c = 0; c < 8; c++)
#pragma unroll
        for (int p = 0; p < 4; p++) {
            float2 v = unpack2(acc[c][p]);
            *reinterpret_cast<__half2*>(&sHh[(cb + c) * 128 + ngb + 2 * p]) =
                __floats2half2_rn(fmaxf(v.x + b1v[c], 0.f), fmaxf(v.y + b1v[c], 0.f));
        }
    __syncthreads();

    int cbz = cg * 4;
    unsigned long long az[4][4];
#pragma unroll
    for (int c = 0; c < 4; c++)
#pragma unroll
        for (int p = 0; p < 4; p++) az[c][p] = 0ull;

    for (int k = 0; k < 64; k++) {
        uint4 inu = *reinterpret_cast<const uint4*>(&sHh[k * 128 + ngb]);
        unsigned long long in[4];
        h8_to_f32x2(inu, in);
        float4 w = *reinterpret_cast<const float4*>(&sWg[k * 32 + cbz]);
        unsigned long long w0 = pack2(w.x), w1 = pack2(w.y);
        unsigned long long w2 = pack2(w.z), w3 = pack2(w.w);
        fma2(az[0][0], in[0], w0); fma2(az[0][1], in[1], w0);
        fma2(az[0][2], in[2], w0); fma2(az[0][3], in[3], w0);
        fma2(az[1][0], in[0], w1); fma2(az[1][1], in[1], w1);
        fma2(az[1][2], in[2], w1); fma2(az[1][3], in[3], w1);
        fma2(az[2][0], in[0], w2); fma2(az[2][1], in[1], w2);
        fma2(az[2][2], in[2], w2); fma2(az[2][3], in[3], w2);
        fma2(az[3][0], in[0], w3); fma2(az[3][1], in[1], w3);
        fma2(az[3][2], in[2], w3); fma2(az[3][3], in[3], w3);
    }

    float as0 = att_src[cbz], as1 = att_src[cbz + 1];
    float as2 = att_src[cbz + 2], as3 = att_src[cbz + 3];
    float ad0 = att_dst[cbz], ad1 = att_dst[cbz + 1];
    float ad2 = att_dst[cbz + 2], ad3 = att_dst[cbz + 3];
    float* sAsP = sW;
    float* sAdP = sW + 8 * 128;

#pragma unroll
    for (int p = 0; p < 4; p++) {
        float2 v0 = unpack2(az[0][p]);
        float2 v1 = unpack2(az[1][p]);
        float2 v2 = unpack2(az[2][p]);
        float2 v3 = unpack2(az[3][p]);
        int nA = ngb + 2 * p;
        int gA = node0 + nA;
        if (gA < n) {
            __half2 h01 = __floats2half2_rn(v0.x, v1.x);
            __half2 h23 = __floats2half2_rn(v2.x, v3.x);
            uint2 st;
            st.x = *reinterpret_cast<unsigned*>(&h01);
            st.y = *reinterpret_cast<unsigned*>(&h23);
            *reinterpret_cast<uint2*>(g_zh + (size_t)gA * OUT_C + cbz) = st;
        }
        if (gA + 1 < n) {
            __half2 h01 = __floats2half2_rn(v0.y, v1.y);
            __half2 h23 = __floats2half2_rn(v2.y, v3.y);
            uint2 st;
            st.x = *reinterpret_cast<unsigned*>(&h01);
            st.y = *reinterpret_cast<unsigned*>(&h23);
            *reinterpret_cast<uint2*>(g_zh + (size_t)(gA + 1) * OUT_C + cbz) = st;
        }
        sAsP[cg * 128 + nA]     = v0.x * as0 + v1.x * as1 + v2.x * as2 + v3.x * as3;
        sAsP[cg * 128 + nA + 1] = v0.y * as0 + v1.y * as1 + v2.y * as2 + v3.y * as3;
        sAdP[cg * 128 + nA]     = v0.x * ad0 + v1.x * ad1 + v2.x * ad2 + v3.x * ad3;
        sAdP[cg * 128 + nA + 1] = v0.y * ad0 + v1.y * ad1 + v2.y * ad2 + v3.y * ad3;
    }
    __syncthreads();

    {
        int g = node0 + tid;
        if (g < n) {
            float sa = 0.f, sd = 0.f;
#pragma unroll
            for (int c = 0; c < 8; c++) {
                sa += sAsP[c * 128 + tid];
                sd += sAdP[c * 128 + tid];
            }
            g_as[g] = sa;
            g_ad[g] = sd;
        }
    }
}

// ---------------- K6: GAT — 4 nodes per warp, packed f32x2 fma ----------------
__global__ void __launch_bounds__(256) k_gat(const float* __restrict__ b2,
                                             float* __restrict__ out,
                                             int n) {
    int warp = (blockIdx.x * blockDim.x + threadIdx.x) >> 5;
    int lane = threadIdx.x & 31;
    int o = lane >> 3;        // octet / node slot 0..3
    int l8 = lane & 7;
    int g = l8 >> 2;          // group 0..1
    int q = l8 & 3;           // 16B chunk within 64B z row

    int node = warp * 4 + o;
    bool valid = node < n;
    int nodec = valid ? node : (n - 1);

    int beg = g_off[nodec];
    int cnt = g_off[nodec + 1] - beg;
    float ad_ = g_ad[nodec];

    unsigned long long acc[4] = {0ull, 0ull, 0ull, 0ull};
    float sum = 0.f;
    if (valid && g == 0) {                  // self-loop
        float w = __expf(lrelu(g_as[nodec] + ad_) - M_SHIFT);
        sum = w;
        uint4 u = *reinterpret_cast<const uint4*>(g_zh + (size_t)nodec * OUT_C + q * 8);
        fma8p(u, pack2(w), acc);
    }

    int nb = (cnt + 7) >> 3;
    int nbmax = __reduce_max_sync(FULL, nb);

    for (int b = 0; b < nbmax; b++) {
        int kk = b * 8 + l8;
        int s_l = 0;
        float w_l = 0.f;
        if (valid && kk < cnt) {
            s_l = g_adj[beg + kk];
            w_l = __expf(lrelu(g_as[s_l] + ad_) - M_SHIFT);
        }
#pragma unroll
        for (int k = 0; k < 8; k += 2) {
            int srcLane = (o << 3) | (k + g);
            int s0 = __shfl_sync(FULL, s_l, srcLane);
            float w0 = __shfl_sync(FULL, w_l, srcLane);
            if (w0 != 0.f) {
                uint4 u = *reinterpret_cast<const uint4*>(g_zh + (size_t)s0 * OUT_C + q * 8);
                sum += w0;
                fma8p(u, pack2(w0), acc);
            }
        }
    }

    // combine the two groups within each octet (xor 4 keeps octet+q intact)
    sum += __shfl_xor_sync(FULL, sum, 4);
#pragma unroll
    for (int i = 0; i < 4; i++) {
        unsigned long long other = __shfl_xor_sync(FULL, acc[i], 4);
        add2(acc[i], other);
    }

    float inv = 1.0f / sum;
    float ov[8];
#pragma unroll
    for (int i = 0; i < 4; i++) {
        float2 f = unpack2(acc[i]);
        ov[2 * i] = f.x * inv + b2[q * 8 + 2 * i];
        ov[2 * i + 1] = f.y * inv + b2[q * 8 + 2 * i + 1];
    }

    // log_softmax over 32 outputs: 4 q-lanes x 8 values (groups replicated)
    float mx = ov[0];
#pragma unroll
    for (int i = 1; i < 8; i++) mx = fmaxf(mx, ov[i]);
    mx = fmaxf(mx, __shfl_xor_sync(FULL, mx, 1));
    mx = fmaxf(mx, __shfl_xor_sync(FULL, mx, 2));
    float se = 0.f;
#pragma unroll
    for (int i = 0; i < 8; i++) se += __expf(ov[i] - mx);
    se += __shfl_xor_sync(FULL, se, 1);
    se += __shfl_xor_sync(FULL, se, 2);
    float ls = mx + logf(se);

    if (valid && g == 0) {
        float* dstp = out + (size_t)node * OUT_C + q * 8;
        *reinterpret_cast<float4*>(dstp) =
            make_float4(ov[0] - ls, ov[1] - ls, ov[2] - ls, ov[3] - ls);
        *reinterpret_cast<float4*>(dstp + 4) =
            make_float4(ov[4] - ls, ov[5] - ls, ov[6] - ls, ov[7] - ls);
    }
}

// ---------------- launch ----------------
extern "C" void kernel_launch(void* const* d_in, const int* in_sizes, int n_in,
                              void* d_out, int out_size) {
    const float* x       = (const float*)d_in[0];
    const int*   ei      = (const int*)d_in[1];
    const float* W_l     = (const float*)d_in[2];
    const float* W_r     = (const float*)d_in[3];
    const float* b1      = (const float*)d_in[4];
    const float* W_g     = (const float*)d_in[5];
    const float* att_src = (const float*)d_in[6];
    const float* att_dst = (const float*)d_in[7];
    const float* b2      = (const float*)d_in[8];
    float* out = (float*)d_out;

    int N = in_sizes[0] / IN_C;
    int E = in_sizes[1] / 2;
    const int* src = ei;
    const int* dst = ei + E;

    int totalx = N * IN_C;
    unsigned e4 = ((unsigned)E + 3u) / 4u;
    int prep_threads = (totalx / 8 > (int)e4) ? totalx / 8 : (int)e4;
    int nb = (N + 1023) / 1024;

    k_prep<<<(prep_threads + 255) / 256, 256>>>(x, dst, E, totalx);   // 1
    k_scan_lb<<<nb, 1024>>>(N, nb);                                   // 2
    k_fill<<<(e4 + 255u) / 256u, 256>>>(src, dst, E);                 // 3
    k_agg<<<(N + 7) / 8, 256>>>(N);                                   // 4 (profiled)

    size_t smemF = 32768 + 32768 + 8192;   // 72KB
    cudaFuncSetAttribute(k_forward, cudaFuncAttributeMaxDynamicSharedMemorySize,
                         (int)smemF);
    k_forward<<<(N + 127) / 128, 128, smemF>>>(W_l, W_r, b1, W_g,
                                               att_src, att_dst, N);  // 5

    k_gat<<<(N + 31) / 32, 256>>>(b2, out, N);                        // 6
}

// round 17
// speedup vs baseline: 1.0313x; 1.0313x over previous
#include <cuda_runtime.h>
#include <cuda_fp16.h>
#include <cstdint>

#define N_MAX 100000
#define E_MAX 1600000
#define IN_C 64
#define HID_C 64
#define OUT_C 32
#define FULL 0xffffffffu
#define M_SHIFT 16.0f   // constant softmax shift (shift-invariant; scores are O(10))

// ---------------- scratch (no allocations; statics zero-init at load) ----------------
__device__ int   g_cnt[N_MAX];            // hist; zeroed by scan after reading
__device__ int   g_cur[N_MAX];            // fill cursors; zeroed by agg
__device__ int   g_off[N_MAX + 1];
__device__ int   g_adj[E_MAX];            // CSR adjacency (src grouped by dst)
__device__ unsigned long long g_tstate[128];  // lookback states (reset in prep)
__device__ __align__(16) __half g_xh[N_MAX * IN_C];     // fp16 x
__device__ __align__(16) __half g_aggh[N_MAX * IN_C];   // fp16 mean-agg
__device__ __align__(16) __half g_zh[N_MAX * OUT_C];    // fp16 z
__device__ float g_as[N_MAX];
__device__ float g_ad[N_MAX];

__device__ __forceinline__ float lrelu(float v) {
    return v > 0.0f ? v : 0.2f * v;
}

// packed f32x2 helpers (Blackwell) — used ONLY in k_forward (smem-born operands)
__device__ __forceinline__ void fma2(unsigned long long& d,
                                     unsigned long long a,
                                     unsigned long long b) {
    asm("fma.rn.f32x2 %0, %1, %2, %0;" : "+l"(d) : "l"(a), "l"(b));
}
__device__ __forceinline__ unsigned long long pack2(float v) {
    unsigned long long r;
    asm("mov.b64 %0, {%1, %1};" : "=l"(r) : "f"(v));
    return r;
}
__device__ __forceinline__ unsigned long long packf(float a, float b) {
    unsigned long long r;
    asm("mov.b64 %0, {%1, %2};" : "=l"(r) : "f"(a), "f"(b));
    return r;
}
__device__ __forceinline__ float2 unpack2(unsigned long long v) {
    float2 f;
    asm("mov.b64 {%0, %1}, %2;" : "=f"(f.x), "=f"(f.y) : "l"(v));
    return f;
}

// scalar accumulate: 8 halves (one uint4) into float[8]  (R15-proven form)
__device__ __forceinline__ void acc8(uint4 u, float* a) {
    float2 f;
    f = __half22float2(*reinterpret_cast<__half2*>(&u.x)); a[0] += f.x; a[1] += f.y;
    f = __half22float2(*reinterpret_cast<__half2*>(&u.y)); a[2] += f.x; a[3] += f.y;
    f = __half22float2(*reinterpret_cast<__half2*>(&u.z)); a[4] += f.x; a[5] += f.y;
    f = __half22float2(*reinterpret_cast<__half2*>(&u.w)); a[6] += f.x; a[7] += f.y;
}
// scalar fma: 8 halves * w into float[8]
__device__ __forceinline__ void fma8(uint4 u, float w, float* a) {
    float2 f;
    f = __half22float2(*reinterpret_cast<__half2*>(&u.x));
    a[0] = fmaf(w, f.x, a[0]); a[1] = fmaf(w, f.y, a[1]);
    f = __half22float2(*reinterpret_cast<__half2*>(&u.y));
    a[2] = fmaf(w, f.x, a[2]); a[3] = fmaf(w, f.y, a[3]);
    f = __half22float2(*reinterpret_cast<__half2*>(&u.z));
    a[4] = fmaf(w, f.x, a[4]); a[5] = fmaf(w, f.y, a[5]);
    f = __half22float2(*reinterpret_cast<__half2*>(&u.w));
    a[6] = fmaf(w, f.x, a[6]); a[7] = fmaf(w, f.y, a[7]);
}

// unpack uint4 of 8 halves into 4 packed f32x2 regs (forward only)
__device__ __forceinline__ void h8_to_f32x2(uint4 u, unsigned long long* o) {
    float2 f;
    f = __half22float2(*reinterpret_cast<__half2*>(&u.x)); o[0] = packf(f.x, f.y);
    f = __half22float2(*reinterpret_cast<__half2*>(&u.y)); o[1] = packf(f.x, f.y);
    f = __half22float2(*reinterpret_cast<__half2*>(&u.z)); o[2] = packf(f.x, f.y);
    f = __half22float2(*reinterpret_cast<__half2*>(&u.w)); o[3] = packf(f.x, f.y);
}

// ---------------- K1: prep = cvt(x->fp16) + hist(dst) + tstate reset ----------------
__global__ void k_prep(const float* __restrict__ x,
                       const int* __restrict__ dst,
                       int E, int totalx) {
    int i = blockIdx.x * blockDim.x + threadIdx.x;
    if (blockIdx.x == 0 && threadIdx.x < 128) g_tstate[threadIdx.x] = 0ull;

    int i8 = i * 8;
    if (i8 < totalx) {
        float4 a = *reinterpret_cast<const float4*>(x + i8);
        float4 b = *reinterpret_cast<const float4*>(x + i8 + 4);
        __half2 h[4];
        h[0] = __floats2half2_rn(a.x, a.y);
        h[1] = __floats2half2_rn(a.z, a.w);
        h[2] = __floats2half2_rn(b.x, b.y);
        h[3] = __floats2half2_rn(b.z, b.w);
        *reinterpret_cast<uint4*>(g_xh + i8) = *reinterpret_cast<uint4*>(h);
    }
    unsigned e = (unsigned)i * 4u;
    if (e + 4 <= (unsigned)E) {
        int4 d = *reinterpret_cast<const int4*>(dst + e);
        atomicAdd(&g_cnt[d.x], 1);
        atomicAdd(&g_cnt[d.y], 1);
        atomicAdd(&g_cnt[d.z], 1);
        atomicAdd(&g_cnt[d.w], 1);
    } else {
        for (; e < (unsigned)E; e++) atomicAdd(&g_cnt[dst[e]], 1);
    }
}

// ---------------- K2: single-launch decoupled-lookback exclusive scan ----------------
__global__ void __launch_bounds__(1024) k_scan_lb(int n, int nb) {
    __shared__ int wsum[32];
    __shared__ int s_excl;
    int b = blockIdx.x, t = threadIdx.x;
    int lane = t & 31, w = t >> 5;
    int i = b * 1024 + t;

    int v = (i < n) ? g_cnt[i] : 0;
    if (i < n) g_cnt[i] = 0;          // reset for next replay

    int incl = v;
#pragma unroll
    for (int o = 1; o < 32; o <<= 1) {
        int u = __shfl_up_sync(FULL, incl, o);
        if (lane >= o) incl += u;
    }
    if (lane == 31) wsum[w] = incl;
    __syncthreads();
    if (w == 0) {
        int s = wsum[lane];
#pragma unroll
        for (int o = 1; o < 32; o <<= 1) {
            int u = __shfl_up_sync(FULL, s, o);
            if (lane >= o) s += u;
        }
        wsum[lane] = s;
    }
    __syncthreads();
    int blockIncl = incl + (w > 0 ? wsum[w - 1] : 0);
    int total = wsum[31];

    if (t == 0)
        atomicExch(&g_tstate[b], (1ull << 32) | (unsigned long long)(unsigned)total);

    if (t == 0 && b == 0) s_excl = 0;
    if (b > 0 && w == 0) {
        int excl = 0;
        int hi = b - 1;
        while (true) {
            int idx = hi - lane;
            unsigned long long s = 0;
            int st = 0;
            if (idx >= 0) {
                do {
                    s = *(volatile unsigned long long*)&g_tstate[idx];
                    st = (int)(s >> 32);
                } while (st == 0);
            }
            unsigned pm = __ballot_sync(FULL, idx >= 0 && st == 2);
            int val = (idx >= 0) ? (int)(unsigned)s : 0;
            if (pm) {
                int fl = __ffs(pm) - 1;
                int contrib = (lane <= fl) ? val : 0;
#pragma unroll
                for (int o = 16; o > 0; o >>= 1)
                    contrib += __shfl_xor_sync(FULL, contrib, o);
                excl += contrib;
                break;
            } else {
                int contrib = val;
#pragma unroll
                for (int o = 16; o > 0; o >>= 1)
                    contrib += __shfl_xor_sync(FULL, contrib, o);
                excl += contrib;
                hi -= 32;
                if (hi < 0) break;
            }
        }
        if (lane == 0) s_excl = excl;
    }
    __syncthreads();
    int excl = s_excl;

    if (t == 0)
        atomicExch(&g_tstate[b],
                   (2ull << 32) | (unsigned long long)(unsigned)(excl + total));

    if (i < n) g_off[i] = excl + blockIncl - v;
    if (b == nb - 1 && t == 1023) g_off[n] = excl + total;
}

// ---------------- K3: fill adjacency (4 edges/thread) ----------------
__global__ void k_fill(const int* __restrict__ src,
                       const int* __restrict__ dst,
                       int E) {
    unsigned i = (blockIdx.x * blockDim.x + threadIdx.x) * 4u;
    if (i + 4 <= (unsigned)E) {
        int4 d = *reinterpret_cast<const int4*>(dst + i);
        int4 s = *reinterpret_cast<const int4*>(src + i);
        g_adj[g_off[d.x] + atomicAdd(&g_cur[d.x], 1)] = s.x;
        g_adj[g_off[d.y] + atomicAdd(&g_cur[d.y], 1)] = s.y;
        g_adj[g_off[d.z] + atomicAdd(&g_cur[d.z], 1)] = s.z;
        g_adj[g_off[d.w] + atomicAdd(&g_cur[d.w], 1)] = s.w;
    } else {
        for (; i < (unsigned)E; i++) {
            int d = dst[i];
            g_adj[g_off[d] + atomicAdd(&g_cur[d], 1)] = src[i];
        }
    }
}

// ---------------- K4: mean aggregation — two-phase warp gather (R15 form) ----------------
__global__ void k_agg(int n) {
    int node = (blockIdx.x * blockDim.x + threadIdx.x) >> 5;
    int lane = threadIdx.x & 31;
    if (node >= n) return;
    int beg = g_off[node];
    int cnt = g_off[node + 1] - beg;
    if (lane == 0) g_cur[node] = 0;     // reset cursor for next replay
    int grp = lane >> 3;    // 0..3
    int q = lane & 7;       // 0..7

    float aA[8] = {0, 0, 0, 0, 0, 0, 0, 0};
    float aB[8] = {0, 0, 0, 0, 0, 0, 0, 0};

    for (int base = 0; base < cnt; base += 32) {
        int kk = base + lane;
        int s_l = (kk < cnt) ? g_adj[beg + kk] : 0;
        int lim = min(cnt - base, 32);
        for (int k = 0; k < lim; k += 8) {
            int i0 = k + grp;
            int i1 = k + 4 + grp;
            int s0 = __shfl_sync(FULL, s_l, i0 & 31);
            int s1 = __shfl_sync(FULL, s_l, i1 & 31);
            if (i0 < lim) {
                uint4 u = *reinterpret_cast<const uint4*>(g_xh + (size_t)s0 * IN_C + q * 8);
                acc8(u, aA);
            }
            if (i1 < lim) {
                uint4 u = *reinterpret_cast<const uint4*>(g_xh + (size_t)s1 * IN_C + q * 8);
                acc8(u, aB);
            }
        }
    }
#pragma unroll
    for (int i = 0; i < 8; i++) {
        float v = aA[i] + aB[i];
        v += __shfl_xor_sync(FULL, v, 8);
        v += __shfl_xor_sync(FULL, v, 16);
        aA[i] = v;
    }
    float inv = 1.0f / fmaxf((float)cnt, 1.0f);
    if (lane < 8) {
        __half2 h[4];
        h[0] = __floats2half2_rn(aA[0] * inv, aA[1] * inv);
        h[1] = __floats2half2_rn(aA[2] * inv, aA[3] * inv);
        h[2] = __floats2half2_rn(aA[4] * inv, aA[5] * inv);
        h[3] = __floats2half2_rn(aA[6] * inv, aA[7] * inv);
        *reinterpret_cast<uint4*>(g_aggh + (size_t)node * IN_C + q * 8) =
            *reinterpret_cast<uint4*>(h);
    }
}

// ---------------- K5: node forward GEMM — fp16 inputs/h, 128-node tile, 8x8 ----------------
__global__ void __launch_bounds__(128) k_forward(
        const float* __restrict__ W_l,
        const float* __restrict__ W_r,
        const float* __restrict__ b1,
        const float* __restrict__ W_g,
        const float* __restrict__ att_src,
        const float* __restrict__ att_dst,
        int n) {
    extern __shared__ char smraw[];
    __half* sInH = reinterpret_cast<__half*>(smraw);           // 32KB
    float* sW = reinterpret_cast<float*>(smraw + 32768);       // 32KB
    float* sWg = reinterpret_cast<float*>(smraw + 65536);      // 8KB

    int tid = threadIdx.x;
    int node0 = blockIdx.x * 128;

    for (int i = tid; i < 2048; i += 128) {
        int k = i >> 4, q = i & 15;
        const float* sp = (k < 64) ? (W_l + k * 64 + q * 4)
                                   : (W_r + (k - 64) * 64 + q * 4);
        *reinterpret_cast<float4*>(&sW[k * 64 + q * 4]) =
            *reinterpret_cast<const float4*>(sp);
    }
    for (int i = tid; i < 512; i += 128) {
        int k = i >> 3, q = i & 7;
        *reinterpret_cast<float4*>(&sWg[k * 32 + q * 4]) =
            *reinterpret_cast<const float4*>(W_g + k * 32 + q * 4);
    }
    for (int i = tid; i < 1024; i += 128) {
        int c = i >> 6, p = i & 63;
        int n0 = node0 + 2 * p;
        uint4 a = make_uint4(0, 0, 0, 0), b = make_uint4(0, 0, 0, 0);
        if (n0 < n)
            a = (c < 8) ? *reinterpret_cast<const uint4*>(g_aggh + (size_t)n0 * IN_C + c * 8)
                        : *reinterpret_cast<const uint4*>(g_xh + (size_t)n0 * IN_C + (c - 8) * 8);
        if (n0 + 1 < n)
            b = (c < 8) ? *reinterpret_cast<const uint4*>(g_aggh + (size_t)(n0 + 1) * IN_C + c * 8)
                        : *reinterpret_cast<const uint4*>(g_xh + (size_t)(n0 + 1) * IN_C + (c - 8) * 8);
        const __half* ha = reinterpret_cast<const __half*>(&a);
        const __half* hb = reinterpret_cast<const __half*>(&b);
        int kb = c * 8;
#pragma unroll
        for (int j = 0; j < 8; j++)
            *reinterpret_cast<__half2*>(&sInH[(kb + j) * 128 + 2 * p]) =
                __halves2half2(ha[j], hb[j]);
    }
    __syncthreads();

    int ng = tid & 15;
    int cg = tid >> 4;
    int ngb = ng * 8;
    int cb = cg * 8;

    unsigned long long acc[8][4];
#pragma unroll
    for (int c = 0; c < 8; c++)
#pragma unroll
        for (int p = 0; p < 4; p++) acc[c][p] = 0ull;

    for (int k = 0; k < 128; k++) {
        uint4 inu = *reinterpret_cast<const uint4*>(&sInH[k * 128 + ngb]);
        unsigned long long in[4];
        h8_to_f32x2(inu, in);
        float4 wA = *reinterpret_cast<const float4*>(&sW[k * 64 + cb]);
        float4 wB = *reinterpret_cast<const float4*>(&sW[k * 64 + cb + 4]);
        unsigned long long w0 = pack2(wA.x), w1 = pack2(wA.y);
        unsigned long long w2 = pack2(wA.z), w3 = pack2(wA.w);
        unsigned long long w4 = pack2(wB.x), w5 = pack2(wB.y);
        unsigned long long w6 = pack2(wB.z), w7 = pack2(wB.w);
        fma2(acc[0][0], in[0], w0); fma2(acc[0][1], in[1], w0);
        fma2(acc[0][2], in[2], w0); fma2(acc[0][3], in[3], w0);
        fma2(acc[1][0], in[0], w1); fma2(acc[1][1], in[1], w1);
        fma2(acc[1][2], in[2], w1); fma2(acc[1][3], in[3], w1);
        fma2(acc[2][0], in[0], w2); fma2(acc[2][1], in[1], w2);
        fma2(acc[2][2], in[2], w2); fma2(acc[2][3], in[3], w2);
        fma2(acc[3][0], in[0], w3); fma2(acc[3][1], in[1], w3);
        fma2(acc[3][2], in[2], w3); fma2(acc[3][3], in[3], w3);
        fma2(acc[4][0], in[0], w4); fma2(acc[4][1], in[1], w4);
        fma2(acc[4][2], in[2], w4); fma2(acc[4][3], in[3], w4);
        fma2(acc[5][0], in[0], w5); fma2(acc[5][1], in[1], w5);
        fma2(acc[5][2], in[2], w5); fma2(acc[5][3], in[3], w5);
        fma2(acc[6][0], in[0], w6); fma2(acc[6][1], in[1], w6);
        fma2(acc[6][2], in[2], w6); fma2(acc[6][3], in[3], w6);
        fma2(acc[7][0], in[0], w7); fma2(acc[7][1], in[1], w7);
        fma2(acc[7][2], in[2], w7); fma2(acc[7][3], in[3], w7);
    }
    __syncthreads();

    __half* sHh = sInH;
    float b1v[8];
#pragma unroll
    for (int c = 0; c < 8; c++) b1v[c] = b1[cb + c];
#pragma unroll
    for (int c = 0; c < 8; c++)
#pragma unroll
        for (int p = 0; p < 4; p++) {
            float2 v = unpack2(acc[c][p]);
            *reinterpret_cast<__half2*>(&sHh[(cb + c) * 128 + ngb + 2 * p]) =
                __floats2half2_rn(fmaxf(v.x + b1v[c], 0.f), fmaxf(v.y + b1v[c], 0.f));
        }
    __syncthreads();

    int cbz = cg * 4;
    unsigned long long az[4][4];
#pragma unroll
    for (int c = 0; c < 4; c++)
#pragma unroll
        for (int p = 0; p < 4; p++) az[c][p] = 0ull;

    for (int k = 0; k < 64; k++) {
        uint4 inu = *reinterpret_cast<const uint4*>(&sHh[k * 128 + ngb]);
        unsigned long long in[4];
        h8_to_f32x2(inu, in);
        float4 w = *reinterpret_cast<const float4*>(&sWg[k * 32 + cbz]);
        unsigned long long w0 = pack2(w.x), w1 = pack2(w.y);
        unsigned long long w2 = pack2(w.z), w3 = pack2(w.w);
        fma2(az[0][0], in[0], w0); fma2(az[0][1], in[1], w0);
        fma2(az[0][2], in[2], w0); fma2(az[0][3], in[3], w0);
        fma2(az[1][0], in[0], w1); fma2(az[1][1], in[1], w1);
        fma2(az[1][2], in[2], w1); fma2(az[1][3], in[3], w1);
        fma2(az[2][0], in[0], w2); fma2(az[2][1], in[1], w2);
        fma2(az[2][2], in[2], w2); fma2(az[2][3], in[3], w2);
        fma2(az[3][0], in[0], w3); fma2(az[3][1], in[1], w3);
        fma2(az[3][2], in[2], w3); fma2(az[3][3], in[3], w3);
    }

    float as0 = att_src[cbz], as1 = att_src[cbz + 1];
    float as2 = att_src[cbz + 2], as3 = att_src[cbz + 3];
    float ad0 = att_dst[cbz], ad1 = att_dst[cbz + 1];
    float ad2 = att_dst[cbz + 2], ad3 = att_dst[cbz + 3];
    float* sAsP = sW;
    float* sAdP = sW + 8 * 128;

#pragma unroll
    for (int p = 0; p < 4; p++) {
        float2 v0 = unpack2(az[0][p]);
        float2 v1 = unpack2(az[1][p]);
        float2 v2 = unpack2(az[2][p]);
        float2 v3 = unpack2(az[3][p]);
        int nA = ngb + 2 * p;
        int gA = node0 + nA;
        if (gA < n) {
            __half2 h01 = __floats2half2_rn(v0.x, v1.x);
            __half2 h23 = __floats2half2_rn(v2.x, v3.x);
            uint2 st;
            st.x = *reinterpret_cast<unsigned*>(&h01);
            st.y = *reinterpret_cast<unsigned*>(&h23);
            *reinterpret_cast<uint2*>(g_zh + (size_t)gA * OUT_C + cbz) = st;
        }
        if (gA + 1 < n) {
            __half2 h01 = __floats2half2_rn(v0.y, v1.y);
            __half2 h23 = __floats2half2_rn(v2.y, v3.y);
            uint2 st;
            st.x = *reinterpret_cast<unsigned*>(&h01);
            st.y = *reinterpret_cast<unsigned*>(&h23);
            *reinterpret_cast<uint2*>(g_zh + (size_t)(gA + 1) * OUT_C + cbz) = st;
        }
        sAsP[cg * 128 + nA]     = v0.x * as0 + v1.x * as1 + v2.x * as2 + v3.x * as3;
        sAsP[cg * 128 + nA + 1] = v0.y * as0 + v1.y * as1 + v2.y * as2 + v3.y * as3;
        sAdP[cg * 128 + nA]     = v0.x * ad0 + v1.x * ad1 + v2.x * ad2 + v3.x * ad3;
        sAdP[cg * 128 + nA + 1] = v0.y * ad0 + v1.y * ad1 + v2.y * ad2 + v3.y * ad3;
    }
    __syncthreads();

    {
        int g = node0 + tid;
        if (g < n) {
            float sa = 0.f, sd = 0.f;
#pragma unroll
            for (int c = 0; c < 8; c++) {
                sa += sAsP[c * 128 + tid];
                sd += sAdP[c * 128 + tid];
            }
            g_as[g] = sa;
            g_ad[g] = sd;
        }
    }
}

// ---------------- K6: GAT — 4 nodes/warp, double-buffered batches ----------------
// octet o = lane>>3 handles node warp*4+o; within octet: 2 groups x 4 chunk-lanes
__global__ void __launch_bounds__(256) k_gat(const float* __restrict__ b2,
                                             float* __restrict__ out,
                                             int n) {
    int warp = (blockIdx.x * blockDim.x + threadIdx.x) >> 5;
    int lane = threadIdx.x & 31;
    int o = lane >> 3;        // octet / node slot 0..3
    int l8 = lane & 7;
    int g = l8 >> 2;          // group 0..1
    int q = l8 & 3;           // 16B chunk within 64B z row

    int node = warp * 4 + o;
    bool valid = node < n;
    int nodec = valid ? node : (n - 1);

    int beg = g_off[nodec];
    int cnt = g_off[nodec + 1] - beg;
    float ad_ = g_ad[nodec];

    float acc[8] = {0, 0, 0, 0, 0, 0, 0, 0};
    float sum = 0.f;
    if (valid && g == 0) {                  // self-loop
        float w = __expf(lrelu(g_as[nodec] + ad_) - M_SHIFT);
        sum = w;
        uint4 u = *reinterpret_cast<const uint4*>(g_zh + (size_t)nodec * OUT_C + q * 8);
        fma8(u, w, acc);
    }

    int nb = (cnt + 7) >> 3;
    int nbmax = __reduce_max_sync(FULL, nb);

    // prologue: batch 0 front-chain
    int kk0 = l8;
    int sN = 0;
    float wN = 0.f;
    if (valid && kk0 < cnt) {
        sN = g_adj[beg + kk0];
        wN = __expf(lrelu(g_as[sN] + ad_) - M_SHIFT);
    }

    for (int b = 0; b < nbmax; b++) {
        int s_l = sN;
        float w_l = wN;
        // prefetch next batch's front-chain (overlaps with this batch's z-gathers)
        int kk = (b + 1) * 8 + l8;
        sN = 0;
        wN = 0.f;
        if (b + 1 < nbmax && valid && kk < cnt) {
            sN = g_adj[beg + kk];
            wN = __expf(lrelu(g_as[sN] + ad_) - M_SHIFT);
        }
#pragma unroll
        for (int k = 0; k < 8; k += 2) {
            int srcLane = (o << 3) | (k + g);
            int s0 = __shfl_sync(FULL, s_l, srcLane);
            float w0 = __shfl_sync(FULL, w_l, srcLane);
            if (w0 != 0.f) {    // real edges have w>0; padding lanes carry 0
                uint4 u = *reinterpret_cast<const uint4*>(g_zh + (size_t)s0 * OUT_C + q * 8);
                sum += w0;
                fma8(u, w0, acc);
            }
        }
    }

    // combine the two groups within each octet (xor 4 keeps octet+q intact)
    sum += __shfl_xor_sync(FULL, sum, 4);
#pragma unroll
    for (int i = 0; i < 8; i++)
        acc[i] += __shfl_xor_sync(FULL, acc[i], 4);

    float inv = 1.0f / sum;
    float ov[8];
#pragma unroll
    for (int i = 0; i < 8; i++)
        ov[i] = acc[i] * inv + b2[q * 8 + i];

    // log_softmax over 32 outputs: 4 q-lanes x 8 values (groups replicated)
    float mx = ov[0];
#pragma unroll
    for (int i = 1; i < 8; i++) mx = fmaxf(mx, ov[i]);
    mx = fmaxf(mx, __shfl_xor_sync(FULL, mx, 1));
    mx = fmaxf(mx, __shfl_xor_sync(FULL, mx, 2));
    float se = 0.f;
#pragma unroll
    for (int i = 0; i < 8; i++) se += __expf(ov[i] - mx);
    se += __shfl_xor_sync(FULL, se, 1);
    se += __shfl_xor_sync(FULL, se, 2);
    float ls = mx + logf(se);

    if (valid && g == 0) {
        float* dstp = out + (size_t)node * OUT_C + q * 8;
        *reinterpret_cast<float4*>(dstp) =
            make_float4(ov[0] - ls, ov[1] - ls, ov[2] - ls, ov[3] - ls);
        *reinterpret_cast<float4*>(dstp + 4) =
            make_float4(ov[4] - ls, ov[5] - ls, ov[6] - ls, ov[7] - ls);
    }
}

// ---------------- launch ----------------
extern "C" void kernel_launch(void* const* d_in, const int* in_sizes, int n_in,
                              void* d_out, int out_size) {
    const float* x       = (const float*)d_in[0];
    const int*   ei      = (const int*)d_in[1];
    const float* W_l     = (const float*)d_in[2];
    const float* W_r     = (const float*)d_in[3];
    const float* b1      = (const float*)d_in[4];
    const float* W_g     = (const float*)d_in[5];
    const float* att_src = (const float*)d_in[6];
    const float* att_dst = (const float*)d_in[7];
    const float* b2      = (const float*)d_in[8];
    float* out = (float*)d_out;

    int N = in_sizes[0] / IN_C;
    int E = in_sizes[1] / 2;
    const int* src = ei;
    const int* dst = ei + E;

    int totalx = N * IN_C;
    unsigned e4 = ((unsigned)E + 3u) / 4u;
    int prep_threads = (totalx / 8 > (int)e4) ? totalx / 8 : (int)e4;
    int nb = (N + 1023) / 1024;

    k_prep<<<(prep_threads + 255) / 256, 256>>>(x, dst, E, totalx);   // 1
    k_scan_lb<<<nb, 1024>>>(N, nb);                                   // 2
    k_fill<<<(e4 + 255u) / 256u, 256>>>(src, dst, E);                 // 3
    k_agg<<<(N + 7) / 8, 256>>>(N);                                   // 4 (profiled)

    size_t smemF = 32768 + 32768 + 8192;   // 72KB
    cudaFuncSetAttribute(k_forward, cudaFuncAttributeMaxDynamicSharedMemorySize,
                         (int)smemF);
    k_forward<<<(N + 127) / 128, 128, smemF>>>(W_l, W_r, b1, W_g,
                                               att_src, att_dst, N);  // 5

    k_gat<<<(N + 31) / 32, 256>>>(b2, out, N);                        // 6
}